// round 8
// baseline (speedup 1.0000x reference)
#include <cuda_runtime.h>
#include <math.h>

#define NN 50000
#define NE 800000
#define CIN 64
#define KDIM 192   // HID*C_IN
#define COUT 128
#define TOTN (2 * NN)
#define TOTE (2 * NE)
#define NB ((TOTN + 1023) / 1024)   // 98 scan blocks

typedef unsigned long long ull;

// ---- static scratch (no allocations allowed) ----
__device__ int   g_count[TOTN];
__device__ int   g_start[TOTN + 1];
__device__ int   g_cursor[TOTN];
__device__ int   g_partial[128];
__device__ int   g_src_sorted[TOTE];                    // 6.4 MB
__device__ float g_ea_sorted[(size_t)TOTE * 6];         // 38.4 MB
__device__ float g_aggr[(size_t)TOTN * KDIM];           // 76.8 MB

// ---------- f32x2 helpers ----------
__device__ __forceinline__ ull pack2(float lo, float hi) {
    ull r; asm("mov.b64 %0, {%1,%2};" : "=l"(r) : "f"(lo), "f"(hi)); return r;
}
__device__ __forceinline__ void unpack2(ull v, float& lo, float& hi) {
    asm("mov.b64 {%0,%1}, %2;" : "=f"(lo), "=f"(hi) : "l"(v));
}
__device__ __forceinline__ void fma2(ull& d, ull a, ull b) {
    asm("fma.rn.f32x2 %0, %1, %2, %0;" : "+l"(d) : "l"(a), "l"(b));
}
__device__ __forceinline__ float tanh_fast(float v) {
    float r; asm("tanh.approx.f32 %0, %1;" : "=f"(r) : "f"(v)); return r;
}

// ---------------- CSR build ----------------
__global__ void zero_counts_kernel() {
    int i = blockIdx.x * blockDim.x + threadIdx.x;
    if (i < TOTN) g_count[i] = 0;
}

// edge_index is int32 on device (JAX x64 disabled -> astype(int64) is a no-op)
__global__ void hist_kernel(const int* __restrict__ ei0, const int* __restrict__ ei1) {
    int e = blockIdx.x * blockDim.x + threadIdx.x;
    if (e >= TOTE) return;
    int layer = (e >= NE);
    const int* ei = layer ? ei1 : ei0;
    int le = e - layer * NE;
    atomicAdd(&g_count[layer * NN + ei[NE + le]], 1);
}

// joint exclusive scan over g_count[0..TOTN): 3-phase multi-block scan
__global__ void scanA_kernel() {   // per-block reduce -> g_partial
    int i = blockIdx.x * 1024 + threadIdx.x;
    int v = (i < TOTN) ? g_count[i] : 0;
    #pragma unroll
    for (int o = 16; o > 0; o >>= 1) v += __shfl_down_sync(0xffffffffu, v, o);
    __shared__ int ws[32];
    if ((threadIdx.x & 31) == 0) ws[threadIdx.x >> 5] = v;
    __syncthreads();
    if (threadIdx.x < 32) {
        int t = ws[threadIdx.x];
        #pragma unroll
        for (int o = 16; o > 0; o >>= 1) t += __shfl_down_sync(0xffffffffu, t, o);
        if (threadIdx.x == 0) g_partial[blockIdx.x] = t;
    }
}

__global__ void scanB_kernel() {   // exclusive scan of the 98 partials (1 block)
    __shared__ int s[128];
    int tid = threadIdx.x;
    int v = (tid < NB) ? g_partial[tid] : 0;
    s[tid] = v;
    __syncthreads();
    #pragma unroll
    for (int o = 1; o < 128; o <<= 1) {
        int t = (tid >= o) ? s[tid - o] : 0;
        __syncthreads();
        s[tid] += t;
        __syncthreads();
    }
    if (tid < NB) g_partial[tid] = s[tid] - v;   // exclusive block offsets
}

__global__ void scanC_kernel() {   // block-local exclusive scan + offset -> start/cursor
    int tid = threadIdx.x;
    int i = blockIdx.x * 1024 + tid;
    int v = (i < TOTN) ? g_count[i] : 0;
    int lane = tid & 31, wid = tid >> 5;
    int incl = v;
    #pragma unroll
    for (int o = 1; o < 32; o <<= 1) {
        int y = __shfl_up_sync(0xffffffffu, incl, o);
        if (lane >= o) incl += y;
    }
    __shared__ int wsum[32];
    if (lane == 31) wsum[wid] = incl;
    __syncthreads();
    if (tid < 32) {
        int w = wsum[tid];
        #pragma unroll
        for (int o = 1; o < 32; o <<= 1) {
            int y = __shfl_up_sync(0xffffffffu, w, o);
            if (tid >= o) w += y;
        }
        wsum[tid] = w;
    }
    __syncthreads();
    int excl = incl - v + (wid ? wsum[wid - 1] : 0) + g_partial[blockIdx.x];
    if (i < TOTN) { g_start[i] = excl; g_cursor[i] = excl; }
    if (i == 0) g_start[TOTN] = TOTE;
}

__global__ void scatter_kernel(const int* __restrict__ ei0, const float* __restrict__ ea0,
                               const int* __restrict__ ei1, const float* __restrict__ ea1) {
    int e = blockIdx.x * blockDim.x + threadIdx.x;
    if (e >= TOTE) return;
    int layer = (e >= NE);
    const int*   ei = layer ? ei1 : ei0;
    const float* ea = layer ? ea1 : ea0;
    int le = e - layer * NE;
    int dst = ei[NE + le];
    int pos = atomicAdd(&g_cursor[layer * NN + dst], 1);
    g_src_sorted[pos] = ei[le];
    const float2* s = (const float2*)(ea + (size_t)le * 6);     // 24B stride -> 8B aligned
    float2* o = (float2*)(g_ea_sorted + (size_t)pos * 6);
    o[0] = s[0]; o[1] = s[1]; o[2] = s[2];
}

// ---------------- per-node edge aggregation (pull, no atomics) ----------------
// 64 threads per super-node (layer*NN+node); thread c owns channels 3c..3c+2
__global__ void __launch_bounds__(256) edge_aggr_kernel(
    const float* __restrict__ x,
    const float* __restrict__ Win0, const float* __restrict__ bin0,
    const float* __restrict__ Win1, const float* __restrict__ bin1)
{
    int nid = blockIdx.x * 4 + (threadIdx.x >> 6);   // 0..TOTN-1 (TOTN % 4 == 0)
    int c = threadIdx.x & 63;
    int layer = (nid >= NN);
    const float* W_in = layer ? Win1 : Win0;
    const float* b_in = layer ? bin1 : bin0;

    float w0[6], w1[6], w2[6];
    #pragma unroll
    for (int a = 0; a < 6; a++) {
        w0[a] = W_in[a * KDIM + 3 * c + 0];
        w1[a] = W_in[a * KDIM + 3 * c + 1];
        w2[a] = W_in[a * KDIM + 3 * c + 2];
    }
    float b0 = b_in[3 * c + 0], b1 = b_in[3 * c + 1], b2 = b_in[3 * c + 2];

    int s = g_start[nid], eEnd = g_start[nid + 1];

    float acc0 = 0.f, acc1 = 0.f, acc2 = 0.f;
    #pragma unroll 2
    for (int i = s; i < eEnd; i++) {
        int srcv = g_src_sorted[i];
        const float2* ea = (const float2*)(g_ea_sorted + (size_t)i * 6);
        float2 p0 = ea[0], p1 = ea[1], p2 = ea[2];
        float a0 = p0.x, a1 = p0.y, a2 = p1.x, a3 = p1.y, a4 = p2.x, a5 = p2.y;
        float xc = x[srcv * CIN + c];   // coalesced 256B gather, L2-resident

        float s0 = fmaf(a0, w0[0], b0); s0 = fmaf(a1, w0[1], s0); s0 = fmaf(a2, w0[2], s0);
        s0 = fmaf(a3, w0[3], s0); s0 = fmaf(a4, w0[4], s0); s0 = fmaf(a5, w0[5], s0);
        float s1 = fmaf(a0, w1[0], b1); s1 = fmaf(a1, w1[1], s1); s1 = fmaf(a2, w1[2], s1);
        s1 = fmaf(a3, w1[3], s1); s1 = fmaf(a4, w1[4], s1); s1 = fmaf(a5, w1[5], s1);
        float s2 = fmaf(a0, w2[0], b2); s2 = fmaf(a1, w2[1], s2); s2 = fmaf(a2, w2[2], s2);
        s2 = fmaf(a3, w2[3], s2); s2 = fmaf(a4, w2[4], s2); s2 = fmaf(a5, w2[5], s2);

        s0 = fmaxf(s0, 0.f); s1 = fmaxf(s1, 0.f); s2 = fmaxf(s2, 0.f);
        acc0 = fmaf(s0, xc, acc0);
        acc1 = fmaf(s1, xc, acc1);
        acc2 = fmaf(s2, xc, acc2);
    }

    float* o = g_aggr + (size_t)nid * KDIM + 3 * c;
    o[0] = acc0; o[1] = acc1; o[2] = acc2;
}

// ---------------- output GEMM + bias + tanh (f32x2 packed) ----------------
// block: 128 nodes x 128 cols, 256 threads; per thread 8 row-pairs x 4 cols.
// A tile transposed [kk][row] (stride 130: even -> LDS.64 aligned; broadcast reads).
// B tile pre-packed as (b,b) ull so the inner loop has zero packing movs.
__global__ void __launch_bounds__(256) gemm_tanh_kernel(
    const float* __restrict__ Wout0, const float* __restrict__ bout0,
    const float* __restrict__ Wout1, const float* __restrict__ bout1,
    float* __restrict__ out)
{
    int layer = blockIdx.y;
    const float* Wout = layer ? Wout1 : Wout0;
    const float* bout = layer ? bout1 : bout0;
    const float* aggr = g_aggr + (size_t)layer * NN * KDIM;

    __shared__ float As[32][130];   // [kk][row], 16.6 KB
    __shared__ ull   Bs[32][128];   // [kk][col] pre-duplicated pairs, 32 KB

    int tid = threadIdx.x;
    int tx = tid & 31;      // col lane -> cols tx, tx+32, tx+64, tx+96
    int ty = tid >> 5;      // row group -> rows ty*16 .. ty*16+15 (8 pairs)
    int n0 = blockIdx.x * 128;

    ull acc[8][4];
    #pragma unroll
    for (int p = 0; p < 8; p++)
        #pragma unroll
        for (int q = 0; q < 4; q++) acc[p][q] = 0ull;

    for (int k0 = 0; k0 < KDIM; k0 += 32) {
        // A: 128 rows x 32 kk = 4096 floats, 16 per thread; coalesced LDG
        #pragma unroll
        for (int j = 0; j < 16; j++) {
            int idx = tid + 256 * j;
            int r = idx >> 5, kk = idx & 31;
            int n = n0 + r;
            As[kk][r] = (n < NN) ? aggr[(size_t)n * KDIM + k0 + kk] : 0.f;
        }
        // B: 32 kk x 128 cols, packed (b,b); 16 per thread
        #pragma unroll
        for (int j = 0; j < 16; j++) {
            int idx = tid + 256 * j;
            int kk = idx >> 7, cc = idx & 127;
            float b = Wout[(k0 + kk) * COUT + cc];
            Bs[kk][cc] = pack2(b, b);
        }
        __syncthreads();
        #pragma unroll
        for (int kk = 0; kk < 32; kk++) {
            ull a[8];
            #pragma unroll
            for (int p = 0; p < 8; p++)
                a[p] = *reinterpret_cast<const ull*>(&As[kk][ty * 16 + 2 * p]);  // broadcast LDS.64
            #pragma unroll
            for (int q = 0; q < 4; q++) {
                ull bb = Bs[kk][tx + 32 * q];
                #pragma unroll
                for (int p = 0; p < 8; p++) fma2(acc[p][q], a[p], bb);
            }
        }
        __syncthreads();
    }

    #pragma unroll
    for (int q = 0; q < 4; q++) {
        int cc = tx + 32 * q;
        float bv = bout[cc];
        #pragma unroll
        for (int p = 0; p < 8; p++) {
            float lo, hi;
            unpack2(acc[p][q], lo, hi);
            int n = n0 + ty * 16 + 2 * p;
            if (n < NN)     out[(size_t)n * (2 * COUT) + (size_t)layer * COUT + cc]       = tanh_fast(lo + bv);
            if (n + 1 < NN) out[(size_t)(n + 1) * (2 * COUT) + (size_t)layer * COUT + cc] = tanh_fast(hi + bv);
        }
    }
}

extern "C" void kernel_launch(void* const* d_in, const int* in_sizes, int n_in,
                              void* d_out, int out_size) {
    const float* x     = (const float*)d_in[0];
    const int*   ei0   = (const int*)d_in[1];
    const float* ea0   = (const float*)d_in[2];
    const int*   ei1   = (const int*)d_in[3];
    const float* ea1   = (const float*)d_in[4];
    const float* Win0  = (const float*)d_in[5];
    const float* bin0  = (const float*)d_in[6];
    const float* Wout0 = (const float*)d_in[7];
    const float* bout0 = (const float*)d_in[8];
    const float* Win1  = (const float*)d_in[9];
    const float* bin1  = (const float*)d_in[10];
    const float* Wout1 = (const float*)d_in[11];
    const float* bout1 = (const float*)d_in[12];
    float* out = (float*)d_out;
    (void)in_sizes; (void)n_in; (void)out_size;

    zero_counts_kernel<<<(TOTN + 255) / 256, 256>>>();
    hist_kernel<<<(TOTE + 255) / 256, 256>>>(ei0, ei1);
    scanA_kernel<<<NB, 1024>>>();
    scanB_kernel<<<1, 128>>>();
    scanC_kernel<<<NB, 1024>>>();
    scatter_kernel<<<(TOTE + 255) / 256, 256>>>(ei0, ea0, ei1, ea1);

    edge_aggr_kernel<<<TOTN / 4, 256>>>(x, Win0, bin0, Win1, bin1);

    dim3 ggrid((NN + 127) / 128, 2);
    gemm_tanh_kernel<<<ggrid, 256>>>(Wout0, bout0, Wout1, bout1, out);
}

// round 10
// speedup vs baseline: 1.0566x; 1.0566x over previous
#include <cuda_runtime.h>
#include <math.h>

#define NN 50000
#define NE 800000
#define CIN 64
#define KDIM 192   // HID*C_IN
#define COUT 128
#define TOTN (2 * NN)
#define TOTE (2 * NE)
#define NB ((TOTN + 1023) / 1024)   // 98 scan blocks

typedef unsigned long long ull;

// ---- static scratch (no allocations allowed) ----
__device__ int   g_count[TOTN];
__device__ int   g_start[TOTN + 1];
__device__ int   g_cursor[TOTN];
__device__ int   g_partial[128];
__device__ int   g_src_sorted[TOTE];                    // 6.4 MB
__device__ float g_ea_sorted[(size_t)6 * TOTE];         // 38.4 MB, SoA [attr][edge]
__device__ float g_aggr[(size_t)TOTN * KDIM];           // 76.8 MB

// ---------- f32x2 helpers ----------
__device__ __forceinline__ ull pack2(float lo, float hi) {
    ull r; asm("mov.b64 %0, {%1,%2};" : "=l"(r) : "f"(lo), "f"(hi)); return r;
}
__device__ __forceinline__ void unpack2(ull v, float& lo, float& hi) {
    asm("mov.b64 {%0,%1}, %2;" : "=f"(lo), "=f"(hi) : "l"(v));
}
__device__ __forceinline__ void fma2(ull& d, ull a, ull b) {
    asm("fma.rn.f32x2 %0, %1, %2, %0;" : "+l"(d) : "l"(a), "l"(b));
}
__device__ __forceinline__ ull relu2(ull v) {
    float lo, hi;
    unpack2(v, lo, hi);
    return pack2(fmaxf(lo, 0.f), fmaxf(hi, 0.f));   // halves alias register pair -> ~2 FMNMX
}
__device__ __forceinline__ float tanh_fast(float v) {
    float r; asm("tanh.approx.f32 %0, %1;" : "=f"(r) : "f"(v)); return r;
}

// ---------------- CSR build ----------------
__global__ void zero_counts_kernel() {
    int i = blockIdx.x * blockDim.x + threadIdx.x;
    if (i < TOTN) g_count[i] = 0;
}

// edge_index is int32 on device (JAX x64 disabled -> astype(int64) is a no-op)
__global__ void hist_kernel(const int* __restrict__ ei0, const int* __restrict__ ei1) {
    int e = blockIdx.x * blockDim.x + threadIdx.x;
    if (e >= TOTE) return;
    int layer = (e >= NE);
    const int* ei = layer ? ei1 : ei0;
    int le = e - layer * NE;
    atomicAdd(&g_count[layer * NN + ei[NE + le]], 1);
}

__global__ void scanA_kernel() {   // per-block reduce -> g_partial
    int i = blockIdx.x * 1024 + threadIdx.x;
    int v = (i < TOTN) ? g_count[i] : 0;
    #pragma unroll
    for (int o = 16; o > 0; o >>= 1) v += __shfl_down_sync(0xffffffffu, v, o);
    __shared__ int ws[32];
    if ((threadIdx.x & 31) == 0) ws[threadIdx.x >> 5] = v;
    __syncthreads();
    if (threadIdx.x < 32) {
        int t = ws[threadIdx.x];
        #pragma unroll
        for (int o = 16; o > 0; o >>= 1) t += __shfl_down_sync(0xffffffffu, t, o);
        if (threadIdx.x == 0) g_partial[blockIdx.x] = t;
    }
}

__global__ void scanB_kernel() {   // exclusive scan of the 98 partials (1 block)
    __shared__ int s[128];
    int tid = threadIdx.x;
    int v = (tid < NB) ? g_partial[tid] : 0;
    s[tid] = v;
    __syncthreads();
    #pragma unroll
    for (int o = 1; o < 128; o <<= 1) {
        int t = (tid >= o) ? s[tid - o] : 0;
        __syncthreads();
        s[tid] += t;
        __syncthreads();
    }
    if (tid < NB) g_partial[tid] = s[tid] - v;
}

__global__ void scanC_kernel() {   // block-local exclusive scan + offset -> start/cursor
    int tid = threadIdx.x;
    int i = blockIdx.x * 1024 + tid;
    int v = (i < TOTN) ? g_count[i] : 0;
    int lane = tid & 31, wid = tid >> 5;
    int incl = v;
    #pragma unroll
    for (int o = 1; o < 32; o <<= 1) {
        int y = __shfl_up_sync(0xffffffffu, incl, o);
        if (lane >= o) incl += y;
    }
    __shared__ int wsum[32];
    if (lane == 31) wsum[wid] = incl;
    __syncthreads();
    if (tid < 32) {
        int w = wsum[tid];
        #pragma unroll
        for (int o = 1; o < 32; o <<= 1) {
            int y = __shfl_up_sync(0xffffffffu, w, o);
            if (tid >= o) w += y;
        }
        wsum[tid] = w;
    }
    __syncthreads();
    int excl = incl - v + (wid ? wsum[wid - 1] : 0) + g_partial[blockIdx.x];
    if (i < TOTN) { g_start[i] = excl; g_cursor[i] = excl; }
    if (i == 0) g_start[TOTN] = TOTE;
}

// scatter into CSR order; edge attrs go SoA [attr][edge] for paired f32x2 loads
__global__ void scatter_kernel(const int* __restrict__ ei0, const float* __restrict__ ea0,
                               const int* __restrict__ ei1, const float* __restrict__ ea1) {
    int e = blockIdx.x * blockDim.x + threadIdx.x;
    if (e >= TOTE) return;
    int layer = (e >= NE);
    const int*   ei = layer ? ei1 : ei0;
    const float* ea = layer ? ea1 : ea0;
    int le = e - layer * NE;
    int dst = ei[NE + le];
    int pos = atomicAdd(&g_cursor[layer * NN + dst], 1);
    g_src_sorted[pos] = ei[le];
    const float2* s = (const float2*)(ea + (size_t)le * 6);
    float2 p0 = s[0], p1 = s[1], p2 = s[2];
    g_ea_sorted[0 * (size_t)TOTE + pos] = p0.x;
    g_ea_sorted[1 * (size_t)TOTE + pos] = p0.y;
    g_ea_sorted[2 * (size_t)TOTE + pos] = p1.x;
    g_ea_sorted[3 * (size_t)TOTE + pos] = p1.y;
    g_ea_sorted[4 * (size_t)TOTE + pos] = p2.x;
    g_ea_sorted[5 * (size_t)TOTE + pos] = p2.y;
}

// ---------------- per-node edge aggregation (pull, no atomics, f32x2 over edge pairs) ----
// 64 threads per super-node; thread c owns channels 3c..3c+2
__global__ void __launch_bounds__(256) edge_aggr_kernel(
    const float* __restrict__ x,
    const float* __restrict__ Win0, const float* __restrict__ bin0,
    const float* __restrict__ Win1, const float* __restrict__ bin1)
{
    int nid = blockIdx.x * 4 + (threadIdx.x >> 6);   // 0..TOTN-1
    int c = threadIdx.x & 63;
    int layer = (nid >= NN);
    const float* W_in = layer ? Win1 : Win0;
    const float* b_in = layer ? bin1 : bin0;

    float w0[6], w1[6], w2[6];
    ull w0p[6], w1p[6], w2p[6];
    #pragma unroll
    for (int a = 0; a < 6; a++) {
        w0[a] = W_in[a * KDIM + 3 * c + 0];
        w1[a] = W_in[a * KDIM + 3 * c + 1];
        w2[a] = W_in[a * KDIM + 3 * c + 2];
        w0p[a] = pack2(w0[a], w0[a]);
        w1p[a] = pack2(w1[a], w1[a]);
        w2p[a] = pack2(w2[a], w2[a]);
    }
    float b0 = b_in[3 * c + 0], b1 = b_in[3 * c + 1], b2 = b_in[3 * c + 2];
    ull b0p = pack2(b0, b0), b1p = pack2(b1, b1), b2p = pack2(b2, b2);

    int s = g_start[nid], eEnd = g_start[nid + 1];

    ull acc0 = 0ull, acc1 = 0ull, acc2 = 0ull;       // pair accumulators
    float z0 = 0.f, z1 = 0.f, z2 = 0.f;              // scalar head/tail accumulators

    int i = s;
    // scalar head to even-align the pair loop (LDG.64 needs even index)
    if (i < eEnd && (i & 1)) {
        int srcv = g_src_sorted[i];
        float a0 = g_ea_sorted[0 * (size_t)TOTE + i], a1 = g_ea_sorted[1 * (size_t)TOTE + i];
        float a2 = g_ea_sorted[2 * (size_t)TOTE + i], a3 = g_ea_sorted[3 * (size_t)TOTE + i];
        float a4 = g_ea_sorted[4 * (size_t)TOTE + i], a5 = g_ea_sorted[5 * (size_t)TOTE + i];
        float xc = x[srcv * CIN + c];
        float s0 = fmaf(a0, w0[0], b0); s0 = fmaf(a1, w0[1], s0); s0 = fmaf(a2, w0[2], s0);
        s0 = fmaf(a3, w0[3], s0); s0 = fmaf(a4, w0[4], s0); s0 = fmaf(a5, w0[5], s0);
        float s1 = fmaf(a0, w1[0], b1); s1 = fmaf(a1, w1[1], s1); s1 = fmaf(a2, w1[2], s1);
        s1 = fmaf(a3, w1[3], s1); s1 = fmaf(a4, w1[4], s1); s1 = fmaf(a5, w1[5], s1);
        float s2 = fmaf(a0, w2[0], b2); s2 = fmaf(a1, w2[1], s2); s2 = fmaf(a2, w2[2], s2);
        s2 = fmaf(a3, w2[3], s2); s2 = fmaf(a4, w2[4], s2); s2 = fmaf(a5, w2[5], s2);
        z0 = fmaf(fmaxf(s0, 0.f), xc, z0);
        z1 = fmaf(fmaxf(s1, 0.f), xc, z1);
        z2 = fmaf(fmaxf(s2, 0.f), xc, z2);
        i++;
    }
    // paired main loop: 2 edges per iteration, all math in f32x2
    for (; i + 1 < eEnd; i += 2) {
        int2 sp = *reinterpret_cast<const int2*>(&g_src_sorted[i]);
        ull a0 = *reinterpret_cast<const ull*>(&g_ea_sorted[0 * (size_t)TOTE + i]);
        ull a1 = *reinterpret_cast<const ull*>(&g_ea_sorted[1 * (size_t)TOTE + i]);
        ull a2 = *reinterpret_cast<const ull*>(&g_ea_sorted[2 * (size_t)TOTE + i]);
        ull a3 = *reinterpret_cast<const ull*>(&g_ea_sorted[3 * (size_t)TOTE + i]);
        ull a4 = *reinterpret_cast<const ull*>(&g_ea_sorted[4 * (size_t)TOTE + i]);
        ull a5 = *reinterpret_cast<const ull*>(&g_ea_sorted[5 * (size_t)TOTE + i]);
        float x0 = x[sp.x * CIN + c];
        float x1 = x[sp.y * CIN + c];
        ull xp = pack2(x0, x1);

        ull s0 = b0p, s1 = b1p, s2 = b2p;
        fma2(s0, a0, w0p[0]); fma2(s0, a1, w0p[1]); fma2(s0, a2, w0p[2]);
        fma2(s0, a3, w0p[3]); fma2(s0, a4, w0p[4]); fma2(s0, a5, w0p[5]);
        fma2(s1, a0, w1p[0]); fma2(s1, a1, w1p[1]); fma2(s1, a2, w1p[2]);
        fma2(s1, a3, w1p[3]); fma2(s1, a4, w1p[4]); fma2(s1, a5, w1p[5]);
        fma2(s2, a0, w2p[0]); fma2(s2, a1, w2p[1]); fma2(s2, a2, w2p[2]);
        fma2(s2, a3, w2p[3]); fma2(s2, a4, w2p[4]); fma2(s2, a5, w2p[5]);

        fma2(acc0, relu2(s0), xp);
        fma2(acc1, relu2(s1), xp);
        fma2(acc2, relu2(s2), xp);
    }
    // scalar tail
    if (i < eEnd) {
        int srcv = g_src_sorted[i];
        float a0 = g_ea_sorted[0 * (size_t)TOTE + i], a1 = g_ea_sorted[1 * (size_t)TOTE + i];
        float a2 = g_ea_sorted[2 * (size_t)TOTE + i], a3 = g_ea_sorted[3 * (size_t)TOTE + i];
        float a4 = g_ea_sorted[4 * (size_t)TOTE + i], a5 = g_ea_sorted[5 * (size_t)TOTE + i];
        float xc = x[srcv * CIN + c];
        float s0 = fmaf(a0, w0[0], b0); s0 = fmaf(a1, w0[1], s0); s0 = fmaf(a2, w0[2], s0);
        s0 = fmaf(a3, w0[3], s0); s0 = fmaf(a4, w0[4], s0); s0 = fmaf(a5, w0[5], s0);
        float s1 = fmaf(a0, w1[0], b1); s1 = fmaf(a1, w1[1], s1); s1 = fmaf(a2, w1[2], s1);
        s1 = fmaf(a3, w1[3], s1); s1 = fmaf(a4, w1[4], s1); s1 = fmaf(a5, w1[5], s1);
        float s2 = fmaf(a0, w2[0], b2); s2 = fmaf(a1, w2[1], s2); s2 = fmaf(a2, w2[2], s2);
        s2 = fmaf(a3, w2[3], s2); s2 = fmaf(a4, w2[4], s2); s2 = fmaf(a5, w2[5], s2);
        z0 = fmaf(fmaxf(s0, 0.f), xc, z0);
        z1 = fmaf(fmaxf(s1, 0.f), xc, z1);
        z2 = fmaf(fmaxf(s2, 0.f), xc, z2);
    }

    float lo, hi;
    unpack2(acc0, lo, hi); z0 += lo + hi;
    unpack2(acc1, lo, hi); z1 += lo + hi;
    unpack2(acc2, lo, hi); z2 += lo + hi;

    float* o = g_aggr + (size_t)nid * KDIM + 3 * c;
    o[0] = z0; o[1] = z1; o[2] = z2;
}

// ---------------- output GEMM + bias + tanh (f32x2, 64x128 tile: 2 CTAs/SM) ----------
__global__ void __launch_bounds__(256) gemm_tanh_kernel(
    const float* __restrict__ Wout0, const float* __restrict__ bout0,
    const float* __restrict__ Wout1, const float* __restrict__ bout1,
    float* __restrict__ out)
{
    int layer = blockIdx.y;
    const float* Wout = layer ? Wout1 : Wout0;
    const float* bout = layer ? bout1 : bout0;
    const float* aggr = g_aggr + (size_t)layer * NN * KDIM;

    __shared__ float As[32][66];    // [kk][row], pairs 8B-aligned
    __shared__ ull   Bs[32][128];   // [kk][col] pre-duplicated (b,b)

    int tid = threadIdx.x;
    int tx = tid & 31;
    int ty = tid >> 5;
    int n0 = blockIdx.x * 64;

    ull acc[4][4];
    #pragma unroll
    for (int p = 0; p < 4; p++)
        #pragma unroll
        for (int q = 0; q < 4; q++) acc[p][q] = 0ull;

    for (int k0 = 0; k0 < KDIM; k0 += 32) {
        #pragma unroll
        for (int j = 0; j < 8; j++) {
            int idx = tid + 256 * j;
            int r = idx >> 5, kk = idx & 31;
            int n = n0 + r;
            As[kk][r] = (n < NN) ? aggr[(size_t)n * KDIM + k0 + kk] : 0.f;
        }
        #pragma unroll
        for (int j = 0; j < 16; j++) {
            int idx = tid + 256 * j;
            int kk = idx >> 7, cc = idx & 127;
            float b = Wout[(k0 + kk) * COUT + cc];
            Bs[kk][cc] = pack2(b, b);
        }
        __syncthreads();
        #pragma unroll
        for (int kk = 0; kk < 32; kk++) {
            ull a[4];
            #pragma unroll
            for (int p = 0; p < 4; p++)
                a[p] = *reinterpret_cast<const ull*>(&As[kk][ty * 8 + 2 * p]);  // broadcast LDS.64
            #pragma unroll
            for (int q = 0; q < 4; q++) {
                ull bb = Bs[kk][tx + 32 * q];
                #pragma unroll
                for (int p = 0; p < 4; p++) fma2(acc[p][q], a[p], bb);
            }
        }
        __syncthreads();
    }

    #pragma unroll
    for (int q = 0; q < 4; q++) {
        int cc = tx + 32 * q;
        float bv = bout[cc];
        #pragma unroll
        for (int p = 0; p < 4; p++) {
            float lo, hi;
            unpack2(acc[p][q], lo, hi);
            int n = n0 + ty * 8 + 2 * p;
            if (n < NN)     out[(size_t)n * (2 * COUT) + (size_t)layer * COUT + cc]       = tanh_fast(lo + bv);
            if (n + 1 < NN) out[(size_t)(n + 1) * (2 * COUT) + (size_t)layer * COUT + cc] = tanh_fast(hi + bv);
        }
    }
}

extern "C" void kernel_launch(void* const* d_in, const int* in_sizes, int n_in,
                              void* d_out, int out_size) {
    const float* x     = (const float*)d_in[0];
    const int*   ei0   = (const int*)d_in[1];
    const float* ea0   = (const float*)d_in[2];
    const int*   ei1   = (const int*)d_in[3];
    const float* ea1   = (const float*)d_in[4];
    const float* Win0  = (const float*)d_in[5];
    const float* bin0  = (const float*)d_in[6];
    const float* Wout0 = (const float*)d_in[7];
    const float* bout0 = (const float*)d_in[8];
    const float* Win1  = (const float*)d_in[9];
    const float* bin1  = (const float*)d_in[10];
    const float* Wout1 = (const float*)d_in[11];
    const float* bout1 = (const float*)d_in[12];
    float* out = (float*)d_out;
    (void)in_sizes; (void)n_in; (void)out_size;

    zero_counts_kernel<<<(TOTN + 255) / 256, 256>>>();
    hist_kernel<<<(TOTE + 255) / 256, 256>>>(ei0, ei1);
    scanA_kernel<<<NB, 1024>>>();
    scanB_kernel<<<1, 128>>>();
    scanC_kernel<<<NB, 1024>>>();
    scatter_kernel<<<(TOTE + 255) / 256, 256>>>(ei0, ea0, ei1, ea1);

    edge_aggr_kernel<<<TOTN / 4, 256>>>(x, Win0, bin0, Win1, bin1);

    dim3 ggrid((NN + 63) / 64, 2);
    gemm_tanh_kernel<<<ggrid, 256>>>(Wout0, bout0, Wout1, bout1, out);
}

// round 11
// speedup vs baseline: 1.1108x; 1.0513x over previous
#include <cuda_runtime.h>
#include <math.h>

#define NN 50000
#define NE 800000
#define CIN 64
#define KDIM 192   // HID*C_IN
#define COUT 128
#define TOTN (2 * NN)
#define TOTE (2 * NE)
#define NB ((TOTN + 1023) / 1024)   // 98 scan blocks

typedef unsigned long long ull;

// ---- static scratch (no allocations allowed) ----
__device__ int   g_count[TOTN];
__device__ int   g_start[TOTN + 1];
__device__ int   g_cursor[TOTN];
__device__ int   g_partial[128];
__device__ int   g_src_sorted[TOTE];                    // 6.4 MB
__device__ float g_ea_sorted[(size_t)TOTE * 6];         // 38.4 MB, AoS [edge][attr]
__device__ float g_aggr[(size_t)TOTN * KDIM];           // 76.8 MB

// ---------- f32x2 helpers ----------
__device__ __forceinline__ ull pack2(float lo, float hi) {
    ull r; asm("mov.b64 %0, {%1,%2};" : "=l"(r) : "f"(lo), "f"(hi)); return r;
}
__device__ __forceinline__ void unpack2(ull v, float& lo, float& hi) {
    asm("mov.b64 {%0,%1}, %2;" : "=f"(lo), "=f"(hi) : "l"(v));
}
__device__ __forceinline__ void fma2(ull& d, ull a, ull b) {
    asm("fma.rn.f32x2 %0, %1, %2, %0;" : "+l"(d) : "l"(a), "l"(b));
}
__device__ __forceinline__ float tanh_fast(float v) {
    float r; asm("tanh.approx.f32 %0, %1;" : "=f"(r) : "f"(v)); return r;
}

// ---------------- CSR build ----------------
__global__ void zero_counts_kernel() {
    int i = blockIdx.x * blockDim.x + threadIdx.x;
    if (i < TOTN) g_count[i] = 0;
}

// edge_index is int32 on device (JAX x64 disabled -> astype(int64) is a no-op)
__global__ void hist_kernel(const int* __restrict__ ei0, const int* __restrict__ ei1) {
    int e = blockIdx.x * blockDim.x + threadIdx.x;
    if (e >= TOTE) return;
    int layer = (e >= NE);
    const int* ei = layer ? ei1 : ei0;
    int le = e - layer * NE;
    atomicAdd(&g_count[layer * NN + ei[NE + le]], 1);
}

__global__ void scanA_kernel() {   // per-block reduce -> g_partial
    int i = blockIdx.x * 1024 + threadIdx.x;
    int v = (i < TOTN) ? g_count[i] : 0;
    #pragma unroll
    for (int o = 16; o > 0; o >>= 1) v += __shfl_down_sync(0xffffffffu, v, o);
    __shared__ int ws[32];
    if ((threadIdx.x & 31) == 0) ws[threadIdx.x >> 5] = v;
    __syncthreads();
    if (threadIdx.x < 32) {
        int t = ws[threadIdx.x];
        #pragma unroll
        for (int o = 16; o > 0; o >>= 1) t += __shfl_down_sync(0xffffffffu, t, o);
        if (threadIdx.x == 0) g_partial[blockIdx.x] = t;
    }
}

__global__ void scanB_kernel() {   // exclusive scan of the 98 partials (1 block)
    __shared__ int s[128];
    int tid = threadIdx.x;
    int v = (tid < NB) ? g_partial[tid] : 0;
    s[tid] = v;
    __syncthreads();
    #pragma unroll
    for (int o = 1; o < 128; o <<= 1) {
        int t = (tid >= o) ? s[tid - o] : 0;
        __syncthreads();
        s[tid] += t;
        __syncthreads();
    }
    if (tid < NB) g_partial[tid] = s[tid] - v;
}

__global__ void scanC_kernel() {   // block-local exclusive scan + offset -> start/cursor
    int tid = threadIdx.x;
    int i = blockIdx.x * 1024 + tid;
    int v = (i < TOTN) ? g_count[i] : 0;
    int lane = tid & 31, wid = tid >> 5;
    int incl = v;
    #pragma unroll
    for (int o = 1; o < 32; o <<= 1) {
        int y = __shfl_up_sync(0xffffffffu, incl, o);
        if (lane >= o) incl += y;
    }
    __shared__ int wsum[32];
    if (lane == 31) wsum[wid] = incl;
    __syncthreads();
    if (tid < 32) {
        int w = wsum[tid];
        #pragma unroll
        for (int o = 1; o < 32; o <<= 1) {
            int y = __shfl_up_sync(0xffffffffu, w, o);
            if (tid >= o) w += y;
        }
        wsum[tid] = w;
    }
    __syncthreads();
    int excl = incl - v + (wid ? wsum[wid - 1] : 0) + g_partial[blockIdx.x];
    if (i < TOTN) { g_start[i] = excl; g_cursor[i] = excl; }
    if (i == 0) g_start[TOTN] = TOTE;
}

__global__ void scatter_kernel(const int* __restrict__ ei0, const float* __restrict__ ea0,
                               const int* __restrict__ ei1, const float* __restrict__ ea1) {
    int e = blockIdx.x * blockDim.x + threadIdx.x;
    if (e >= TOTE) return;
    int layer = (e >= NE);
    const int*   ei = layer ? ei1 : ei0;
    const float* ea = layer ? ea1 : ea0;
    int le = e - layer * NE;
    int dst = ei[NE + le];
    int pos = atomicAdd(&g_cursor[layer * NN + dst], 1);
    g_src_sorted[pos] = ei[le];
    const float2* s = (const float2*)(ea + (size_t)le * 6);     // 24B stride -> 8B aligned
    float2* o = (float2*)(g_ea_sorted + (size_t)pos * 6);
    o[0] = s[0]; o[1] = s[1]; o[2] = s[2];
}

// ---------------- per-node edge aggregation (pull, no atomics; scalar, AoS) ----------
// 64 threads per super-node (layer*NN+node); thread c owns channels 3c..3c+2
__global__ void __launch_bounds__(256) edge_aggr_kernel(
    const float* __restrict__ x,
    const float* __restrict__ Win0, const float* __restrict__ bin0,
    const float* __restrict__ Win1, const float* __restrict__ bin1)
{
    int nid = blockIdx.x * 4 + (threadIdx.x >> 6);   // 0..TOTN-1 (TOTN % 4 == 0)
    int c = threadIdx.x & 63;
    int layer = (nid >= NN);
    const float* W_in = layer ? Win1 : Win0;
    const float* b_in = layer ? bin1 : bin0;

    float w0[6], w1[6], w2[6];
    #pragma unroll
    for (int a = 0; a < 6; a++) {
        w0[a] = W_in[a * KDIM + 3 * c + 0];
        w1[a] = W_in[a * KDIM + 3 * c + 1];
        w2[a] = W_in[a * KDIM + 3 * c + 2];
    }
    float b0 = b_in[3 * c + 0], b1 = b_in[3 * c + 1], b2 = b_in[3 * c + 2];

    int s = g_start[nid], eEnd = g_start[nid + 1];

    float acc0 = 0.f, acc1 = 0.f, acc2 = 0.f;
    #pragma unroll 2
    for (int i = s; i < eEnd; i++) {
        int srcv = g_src_sorted[i];
        const float2* ea = (const float2*)(g_ea_sorted + (size_t)i * 6);
        float2 p0 = ea[0], p1 = ea[1], p2 = ea[2];
        float a0 = p0.x, a1 = p0.y, a2 = p1.x, a3 = p1.y, a4 = p2.x, a5 = p2.y;
        float xc = x[srcv * CIN + c];   // coalesced 256B gather, L2-resident

        float s0 = fmaf(a0, w0[0], b0); s0 = fmaf(a1, w0[1], s0); s0 = fmaf(a2, w0[2], s0);
        s0 = fmaf(a3, w0[3], s0); s0 = fmaf(a4, w0[4], s0); s0 = fmaf(a5, w0[5], s0);
        float s1 = fmaf(a0, w1[0], b1); s1 = fmaf(a1, w1[1], s1); s1 = fmaf(a2, w1[2], s1);
        s1 = fmaf(a3, w1[3], s1); s1 = fmaf(a4, w1[4], s1); s1 = fmaf(a5, w1[5], s1);
        float s2 = fmaf(a0, w2[0], b2); s2 = fmaf(a1, w2[1], s2); s2 = fmaf(a2, w2[2], s2);
        s2 = fmaf(a3, w2[3], s2); s2 = fmaf(a4, w2[4], s2); s2 = fmaf(a5, w2[5], s2);

        s0 = fmaxf(s0, 0.f); s1 = fmaxf(s1, 0.f); s2 = fmaxf(s2, 0.f);
        acc0 = fmaf(s0, xc, acc0);
        acc1 = fmaf(s1, xc, acc1);
        acc2 = fmaf(s2, xc, acc2);
    }

    float* o = g_aggr + (size_t)nid * KDIM + 3 * c;
    o[0] = acc0; o[1] = acc1; o[2] = acc2;
}

// ---------------- output GEMM + bias + tanh (f32x2, 64x128 tile: 2 CTAs/SM) ----------
// A tile transposed [kk][row] (pairs 8B-aligned, broadcast LDS.64).
// B tile pre-packed as (b,b) ull so the inner loop has zero packing movs.
__global__ void __launch_bounds__(256) gemm_tanh_kernel(
    const float* __restrict__ Wout0, const float* __restrict__ bout0,
    const float* __restrict__ Wout1, const float* __restrict__ bout1,
    float* __restrict__ out)
{
    int layer = blockIdx.y;
    const float* Wout = layer ? Wout1 : Wout0;
    const float* bout = layer ? bout1 : bout0;
    const float* aggr = g_aggr + (size_t)layer * NN * KDIM;

    __shared__ float As[32][66];    // [kk][row]
    __shared__ ull   Bs[32][128];   // [kk][col] pre-duplicated (b,b)

    int tid = threadIdx.x;
    int tx = tid & 31;
    int ty = tid >> 5;
    int n0 = blockIdx.x * 64;

    ull acc[4][4];
    #pragma unroll
    for (int p = 0; p < 4; p++)
        #pragma unroll
        for (int q = 0; q < 4; q++) acc[p][q] = 0ull;

    for (int k0 = 0; k0 < KDIM; k0 += 32) {
        #pragma unroll
        for (int j = 0; j < 8; j++) {
            int idx = tid + 256 * j;
            int r = idx >> 5, kk = idx & 31;
            int n = n0 + r;
            As[kk][r] = (n < NN) ? aggr[(size_t)n * KDIM + k0 + kk] : 0.f;
        }
        #pragma unroll
        for (int j = 0; j < 16; j++) {
            int idx = tid + 256 * j;
            int kk = idx >> 7, cc = idx & 127;
            float b = Wout[(k0 + kk) * COUT + cc];
            Bs[kk][cc] = pack2(b, b);
        }
        __syncthreads();
        #pragma unroll
        for (int kk = 0; kk < 32; kk++) {
            ull a[4];
            #pragma unroll
            for (int p = 0; p < 4; p++)
                a[p] = *reinterpret_cast<const ull*>(&As[kk][ty * 8 + 2 * p]);  // broadcast LDS.64
            #pragma unroll
            for (int q = 0; q < 4; q++) {
                ull bb = Bs[kk][tx + 32 * q];
                #pragma unroll
                for (int p = 0; p < 4; p++) fma2(acc[p][q], a[p], bb);
            }
        }
        __syncthreads();
    }

    #pragma unroll
    for (int q = 0; q < 4; q++) {
        int cc = tx + 32 * q;
        float bv = bout[cc];
        #pragma unroll
        for (int p = 0; p < 4; p++) {
            float lo, hi;
            unpack2(acc[p][q], lo, hi);
            int n = n0 + ty * 8 + 2 * p;
            if (n < NN)     out[(size_t)n * (2 * COUT) + (size_t)layer * COUT + cc]       = tanh_fast(lo + bv);
            if (n + 1 < NN) out[(size_t)(n + 1) * (2 * COUT) + (size_t)layer * COUT + cc] = tanh_fast(hi + bv);
        }
    }
}

extern "C" void kernel_launch(void* const* d_in, const int* in_sizes, int n_in,
                              void* d_out, int out_size) {
    const float* x     = (const float*)d_in[0];
    const int*   ei0   = (const int*)d_in[1];
    const float* ea0   = (const float*)d_in[2];
    const int*   ei1   = (const int*)d_in[3];
    const float* ea1   = (const float*)d_in[4];
    const float* Win0  = (const float*)d_in[5];
    const float* bin0  = (const float*)d_in[6];
    const float* Wout0 = (const float*)d_in[7];
    const float* bout0 = (const float*)d_in[8];
    const float* Win1  = (const float*)d_in[9];
    const float* bin1  = (const float*)d_in[10];
    const float* Wout1 = (const float*)d_in[11];
    const float* bout1 = (const float*)d_in[12];
    float* out = (float*)d_out;
    (void)in_sizes; (void)n_in; (void)out_size;

    zero_counts_kernel<<<(TOTN + 255) / 256, 256>>>();
    hist_kernel<<<(TOTE + 255) / 256, 256>>>(ei0, ei1);
    scanA_kernel<<<NB, 1024>>>();
    scanB_kernel<<<1, 128>>>();
    scanC_kernel<<<NB, 1024>>>();
    scatter_kernel<<<(TOTE + 255) / 256, 256>>>(ei0, ea0, ei1, ea1);

    edge_aggr_kernel<<<TOTN / 4, 256>>>(x, Win0, bin0, Win1, bin1);

    dim3 ggrid((NN + 63) / 64, 2);
    gemm_tanh_kernel<<<ggrid, 256>>>(Wout0, bout0, Wout1, bout1, out);
}

// round 13
// speedup vs baseline: 1.1836x; 1.0656x over previous
#include <cuda_runtime.h>
#include <math.h>

#define NN 50000
#define NE 800000
#define CIN 64
#define KDIM 192   // HID*C_IN
#define COUT 128
#define TOTN (2 * NN)
#define TOTE (2 * NE)
#define NB ((TOTN + 1023) / 1024)   // 98 scan blocks

typedef unsigned long long ull;

// ---- static scratch (no allocations allowed) ----
__device__ int   g_count[TOTN];
__device__ int   g_start[TOTN + 1];
__device__ int   g_cursor[TOTN];
__device__ int   g_partial[128];
__device__ int   g_src_sorted[TOTE];                    // 6.4 MB
__device__ float g_ea_sorted[(size_t)TOTE * 6];         // 38.4 MB, AoS [edge][attr]
__device__ float g_aggr[(size_t)TOTN * KDIM];           // 76.8 MB

// ---------- f32x2 helpers ----------
__device__ __forceinline__ ull pack2(float lo, float hi) {
    ull r; asm("mov.b64 %0, {%1,%2};" : "=l"(r) : "f"(lo), "f"(hi)); return r;
}
__device__ __forceinline__ void unpack2(ull v, float& lo, float& hi) {
    asm("mov.b64 {%0,%1}, %2;" : "=f"(lo), "=f"(hi) : "l"(v));
}
__device__ __forceinline__ void fma2(ull& d, ull a, ull b) {
    asm("fma.rn.f32x2 %0, %1, %2, %0;" : "+l"(d) : "l"(a), "l"(b));
}
__device__ __forceinline__ ull relu2(ull v) {          // halves alias regs: movs rename-free
    float lo, hi;
    unpack2(v, lo, hi);
    return pack2(fmaxf(lo, 0.f), fmaxf(hi, 0.f));
}
__device__ __forceinline__ float tanh_fast(float v) {
    float r; asm("tanh.approx.f32 %0, %1;" : "=f"(r) : "f"(v)); return r;
}

// ---------------- CSR build ----------------
__global__ void zero_counts_kernel() {
    int i = blockIdx.x * blockDim.x + threadIdx.x;
    if (i < TOTN) g_count[i] = 0;
}

// edge_index is int32 on device (JAX x64 disabled -> astype(int64) is a no-op)
__global__ void hist_kernel(const int* __restrict__ ei0, const int* __restrict__ ei1) {
    int e = blockIdx.x * blockDim.x + threadIdx.x;
    if (e >= TOTE) return;
    int layer = (e >= NE);
    const int* ei = layer ? ei1 : ei0;
    int le = e - layer * NE;
    atomicAdd(&g_count[layer * NN + ei[NE + le]], 1);
}

__global__ void scanA_kernel() {   // per-block reduce -> g_partial
    int i = blockIdx.x * 1024 + threadIdx.x;
    int v = (i < TOTN) ? g_count[i] : 0;
    #pragma unroll
    for (int o = 16; o > 0; o >>= 1) v += __shfl_down_sync(0xffffffffu, v, o);
    __shared__ int ws[32];
    if ((threadIdx.x & 31) == 0) ws[threadIdx.x >> 5] = v;
    __syncthreads();
    if (threadIdx.x < 32) {
        int t = ws[threadIdx.x];
        #pragma unroll
        for (int o = 16; o > 0; o >>= 1) t += __shfl_down_sync(0xffffffffu, t, o);
        if (threadIdx.x == 0) g_partial[blockIdx.x] = t;
    }
}

__global__ void scanB_kernel() {   // exclusive scan of the 98 partials (1 block)
    __shared__ int s[128];
    int tid = threadIdx.x;
    int v = (tid < NB) ? g_partial[tid] : 0;
    s[tid] = v;
    __syncthreads();
    #pragma unroll
    for (int o = 1; o < 128; o <<= 1) {
        int t = (tid >= o) ? s[tid - o] : 0;
        __syncthreads();
        s[tid] += t;
        __syncthreads();
    }
    if (tid < NB) g_partial[tid] = s[tid] - v;
}

__global__ void scanC_kernel() {   // block-local exclusive scan + offset -> start/cursor
    int tid = threadIdx.x;
    int i = blockIdx.x * 1024 + tid;
    int v = (i < TOTN) ? g_count[i] : 0;
    int lane = tid & 31, wid = tid >> 5;
    int incl = v;
    #pragma unroll
    for (int o = 1; o < 32; o <<= 1) {
        int y = __shfl_up_sync(0xffffffffu, incl, o);
        if (lane >= o) incl += y;
    }
    __shared__ int wsum[32];
    if (lane == 31) wsum[wid] = incl;
    __syncthreads();
    if (tid < 32) {
        int w = wsum[tid];
        #pragma unroll
        for (int o = 1; o < 32; o <<= 1) {
            int y = __shfl_up_sync(0xffffffffu, w, o);
            if (tid >= o) w += y;
        }
        wsum[tid] = w;
    }
    __syncthreads();
    int excl = incl - v + (wid ? wsum[wid - 1] : 0) + g_partial[blockIdx.x];
    if (i < TOTN) { g_start[i] = excl; g_cursor[i] = excl; }
    if (i == 0) g_start[TOTN] = TOTE;
}

__global__ void scatter_kernel(const int* __restrict__ ei0, const float* __restrict__ ea0,
                               const int* __restrict__ ei1, const float* __restrict__ ea1) {
    int e = blockIdx.x * blockDim.x + threadIdx.x;
    if (e >= TOTE) return;
    int layer = (e >= NE);
    const int*   ei = layer ? ei1 : ei0;
    const float* ea = layer ? ea1 : ea0;
    int le = e - layer * NE;
    int dst = ei[NE + le];
    int pos = atomicAdd(&g_cursor[layer * NN + dst], 1);
    g_src_sorted[pos] = ei[le];
    const float2* s = (const float2*)(ea + (size_t)le * 6);     // 24B stride -> 8B aligned
    float2* o = (float2*)(g_ea_sorted + (size_t)pos * 6);
    o[0] = s[0]; o[1] = s[1]; o[2] = s[2];
}

// ---------------- per-node edge aggregation: f32x2 over ADJACENT CHANNEL pairs ---------
// 32 threads per node; thread t owns channels 2t, 2t+1 -> output dims 6t..6t+5.
// Pair j packs (dim 6t+j, dim 6t+3+j): the x pair (x[2t], x[2t+1]) is one aligned LDG.64.
__global__ void __launch_bounds__(256) edge_aggr_kernel(
    const float* __restrict__ x,
    const float* __restrict__ Win0, const float* __restrict__ bin0,
    const float* __restrict__ Win1, const float* __restrict__ bin1)
{
    int nid = blockIdx.x * 8 + (threadIdx.x >> 5);   // 0..TOTN-1 (TOTN % 8 == 0)
    int t = threadIdx.x & 31;
    int layer = (nid >= NN);
    const float* W_in = layer ? Win1 : Win0;
    const float* b_in = layer ? bin1 : bin0;

    // packed weights: wp[j][a] = (W[a][6t+j], W[a][6t+3+j])
    ull w0p[6], w1p[6], w2p[6];
    #pragma unroll
    for (int a = 0; a < 6; a++) {
        const float* Wr = W_in + a * KDIM + 6 * t;
        w0p[a] = pack2(Wr[0], Wr[3]);
        w1p[a] = pack2(Wr[1], Wr[4]);
        w2p[a] = pack2(Wr[2], Wr[5]);
    }
    const float* br = b_in + 6 * t;
    ull b0p = pack2(br[0], br[3]);
    ull b1p = pack2(br[1], br[4]);
    ull b2p = pack2(br[2], br[5]);

    int s = g_start[nid], eEnd = g_start[nid + 1];

    ull acc0 = 0ull, acc1 = 0ull, acc2 = 0ull;
    for (int i = s; i < eEnd; i++) {
        int srcv = g_src_sorted[i];                     // same addr across warp
        const float2* ea = (const float2*)(g_ea_sorted + (size_t)i * 6);
        float2 p0 = ea[0], p1 = ea[1], p2 = ea[2];      // same addr across warp
        ull a0 = pack2(p0.x, p0.x), a1 = pack2(p0.y, p0.y);
        ull a2 = pack2(p1.x, p1.x), a3 = pack2(p1.y, p1.y);
        ull a4 = pack2(p2.x, p2.x), a5 = pack2(p2.y, p2.y);
        // x pair for channels 2t, 2t+1: contiguous 8B, coalesced across warp
        ull xp = *reinterpret_cast<const ull*>(x + (size_t)srcv * CIN + 2 * t);

        ull s0 = b0p, s1 = b1p, s2 = b2p;
        fma2(s0, a0, w0p[0]); fma2(s0, a1, w0p[1]); fma2(s0, a2, w0p[2]);
        fma2(s0, a3, w0p[3]); fma2(s0, a4, w0p[4]); fma2(s0, a5, w0p[5]);
        fma2(s1, a0, w1p[0]); fma2(s1, a1, w1p[1]); fma2(s1, a2, w1p[2]);
        fma2(s1, a3, w1p[3]); fma2(s1, a4, w1p[4]); fma2(s1, a5, w1p[5]);
        fma2(s2, a0, w2p[0]); fma2(s2, a1, w2p[1]); fma2(s2, a2, w2p[2]);
        fma2(s2, a3, w2p[3]); fma2(s2, a4, w2p[4]); fma2(s2, a5, w2p[5]);

        fma2(acc0, relu2(s0), xp);
        fma2(acc1, relu2(s1), xp);
        fma2(acc2, relu2(s2), xp);
    }

    // unpack: dims 6t+j = lo_j, 6t+3+j = hi_j
    float lo0, hi0, lo1, hi1, lo2, hi2;
    unpack2(acc0, lo0, hi0);
    unpack2(acc1, lo1, hi1);
    unpack2(acc2, lo2, hi2);
    float* o = g_aggr + (size_t)nid * KDIM + 6 * t;
    o[0] = lo0; o[1] = lo1; o[2] = lo2;
    o[3] = hi0; o[4] = hi1; o[5] = hi2;
}

// ---------------- output GEMM + bias + tanh (R6 form: float Bs, pack-in-loop) ---------
__global__ void __launch_bounds__(256) gemm_tanh_kernel(
    const float* __restrict__ Wout0, const float* __restrict__ bout0,
    const float* __restrict__ Wout1, const float* __restrict__ bout1,
    float* __restrict__ out)
{
    int layer = blockIdx.y;
    const float* Wout = layer ? Wout1 : Wout0;
    const float* bout = layer ? bout1 : bout0;
    const float* aggr = g_aggr + (size_t)layer * NN * KDIM;

    __shared__ float As[32][66];    // [kk][row], pairs 8B-aligned
    __shared__ float Bs[32][128];

    int tid = threadIdx.x;
    int tx = tid & 31;
    int ty = tid >> 5;
    int n0 = blockIdx.x * 64;

    ull acc[4][4];
    #pragma unroll
    for (int p = 0; p < 4; p++)
        #pragma unroll
        for (int q = 0; q < 4; q++) acc[p][q] = 0ull;

    for (int k0 = 0; k0 < KDIM; k0 += 32) {
        #pragma unroll
        for (int j = 0; j < 8; j++) {
            int idx = tid + 256 * j;
            int r = idx >> 5, kk = idx & 31;
            int n = n0 + r;
            As[kk][r] = (n < NN) ? aggr[(size_t)n * KDIM + k0 + kk] : 0.f;
        }
        #pragma unroll
        for (int j = 0; j < 16; j++) {
            int idx = tid + 256 * j;
            int kk = idx >> 7, cc = idx & 127;
            Bs[kk][cc] = Wout[(k0 + kk) * COUT + cc];
        }
        __syncthreads();
        #pragma unroll
        for (int kk = 0; kk < 32; kk++) {
            ull a[4];
            #pragma unroll
            for (int p = 0; p < 4; p++)
                a[p] = *reinterpret_cast<const ull*>(&As[kk][ty * 8 + 2 * p]);  // broadcast LDS.64
            #pragma unroll
            for (int q = 0; q < 4; q++) {
                float b = Bs[kk][tx + 32 * q];
                ull bb = pack2(b, b);
                #pragma unroll
                for (int p = 0; p < 4; p++) fma2(acc[p][q], a[p], bb);
            }
        }
        __syncthreads();
    }

    #pragma unroll
    for (int q = 0; q < 4; q++) {
        int cc = tx + 32 * q;
        float bv = bout[cc];
        #pragma unroll
        for (int p = 0; p < 4; p++) {
            float lo, hi;
            unpack2(acc[p][q], lo, hi);
            int n = n0 + ty * 8 + 2 * p;
            if (n < NN)     out[(size_t)n * (2 * COUT) + (size_t)layer * COUT + cc]       = tanh_fast(lo + bv);
            if (n + 1 < NN) out[(size_t)(n + 1) * (2 * COUT) + (size_t)layer * COUT + cc] = tanh_fast(hi + bv);
        }
    }
}

extern "C" void kernel_launch(void* const* d_in, const int* in_sizes, int n_in,
                              void* d_out, int out_size) {
    const float* x     = (const float*)d_in[0];
    const int*   ei0   = (const int*)d_in[1];
    const float* ea0   = (const float*)d_in[2];
    const int*   ei1   = (const int*)d_in[3];
    const float* ea1   = (const float*)d_in[4];
    const float* Win0  = (const float*)d_in[5];
    const float* bin0  = (const float*)d_in[6];
    const float* Wout0 = (const float*)d_in[7];
    const float* bout0 = (const float*)d_in[8];
    const float* Win1  = (const float*)d_in[9];
    const float* bin1  = (const float*)d_in[10];
    const float* Wout1 = (const float*)d_in[11];
    const float* bout1 = (const float*)d_in[12];
    float* out = (float*)d_out;
    (void)in_sizes; (void)n_in; (void)out_size;

    zero_counts_kernel<<<(TOTN + 255) / 256, 256>>>();
    hist_kernel<<<(TOTE + 255) / 256, 256>>>(ei0, ei1);
    scanA_kernel<<<NB, 1024>>>();
    scanB_kernel<<<1, 128>>>();
    scanC_kernel<<<NB, 1024>>>();
    scatter_kernel<<<(TOTE + 255) / 256, 256>>>(ei0, ea0, ei1, ea1);

    edge_aggr_kernel<<<TOTN / 8, 256>>>(x, Win0, bin0, Win1, bin1);

    dim3 ggrid((NN + 63) / 64, 2);
    gemm_tanh_kernel<<<ggrid, 256>>>(Wout0, bout0, Wout1, bout1, out);
}

// round 14
// speedup vs baseline: 1.3760x; 1.1625x over previous
#include <cuda_runtime.h>
#include <math.h>
#include <stdint.h>

#define NN 50000
#define NE 800000
#define CIN 64
#define KDIM 192   // HID*C_IN
#define COUT 128
#define TOTN (2 * NN)
#define TOTE (2 * NE)
#define NB ((TOTN + 1023) / 1024)   // 98 scan blocks

typedef unsigned long long ull;

// ---- static scratch (no allocations allowed) ----
__device__ int   g_count[TOTN];
__device__ int   g_start[TOTN + 1];
__device__ int   g_cursor[TOTN];
__device__ int   g_partial[128];
__device__ int   g_src_sorted[TOTE];                    // 6.4 MB
__device__ float g_ea_sorted[(size_t)TOTE * 6];         // 38.4 MB, AoS [edge][attr]
__device__ float g_aggr[(size_t)TOTN * KDIM];           // 76.8 MB

// ---------- f32x2 / misc helpers ----------
__device__ __forceinline__ ull pack2(float lo, float hi) {
    ull r; asm("mov.b64 %0, {%1,%2};" : "=l"(r) : "f"(lo), "f"(hi)); return r;
}
__device__ __forceinline__ void unpack2(ull v, float& lo, float& hi) {
    asm("mov.b64 {%0,%1}, %2;" : "=f"(lo), "=f"(hi) : "l"(v));
}
__device__ __forceinline__ void fma2(ull& d, ull a, ull b) {
    asm("fma.rn.f32x2 %0, %1, %2, %0;" : "+l"(d) : "l"(a), "l"(b));
}
__device__ __forceinline__ ull relu2(ull v) {
    float lo, hi;
    unpack2(v, lo, hi);
    return pack2(fmaxf(lo, 0.f), fmaxf(hi, 0.f));
}
__device__ __forceinline__ float tanh_fast(float v) {
    float r; asm("tanh.approx.f32 %0, %1;" : "=f"(r) : "f"(v)); return r;
}
__device__ __forceinline__ uint32_t f2tf32(float f) {
    uint32_t u; asm("cvt.rna.tf32.f32 %0, %1;" : "=r"(u) : "f"(f)); return u;
}
__device__ __forceinline__ void mma_tf32(float* c, const uint32_t* a, const uint32_t* b) {
    asm("mma.sync.aligned.m16n8k8.row.col.f32.tf32.tf32.f32 "
        "{%0,%1,%2,%3}, {%4,%5,%6,%7}, {%8,%9}, {%0,%1,%2,%3};"
        : "+f"(c[0]), "+f"(c[1]), "+f"(c[2]), "+f"(c[3])
        : "r"(a[0]), "r"(a[1]), "r"(a[2]), "r"(a[3]), "r"(b[0]), "r"(b[1]));
}

// ---------------- CSR build ----------------
__global__ void zero_counts_kernel() {
    int i = blockIdx.x * blockDim.x + threadIdx.x;
    if (i < TOTN) g_count[i] = 0;
}

// edge_index is int32 on device (JAX x64 disabled -> astype(int64) is a no-op)
__global__ void hist_kernel(const int* __restrict__ ei0, const int* __restrict__ ei1) {
    int e = blockIdx.x * blockDim.x + threadIdx.x;
    if (e >= TOTE) return;
    int layer = (e >= NE);
    const int* ei = layer ? ei1 : ei0;
    int le = e - layer * NE;
    atomicAdd(&g_count[layer * NN + ei[NE + le]], 1);
}

__global__ void scanA_kernel() {   // per-block reduce -> g_partial
    int i = blockIdx.x * 1024 + threadIdx.x;
    int v = (i < TOTN) ? g_count[i] : 0;
    #pragma unroll
    for (int o = 16; o > 0; o >>= 1) v += __shfl_down_sync(0xffffffffu, v, o);
    __shared__ int ws[32];
    if ((threadIdx.x & 31) == 0) ws[threadIdx.x >> 5] = v;
    __syncthreads();
    if (threadIdx.x < 32) {
        int t = ws[threadIdx.x];
        #pragma unroll
        for (int o = 16; o > 0; o >>= 1) t += __shfl_down_sync(0xffffffffu, t, o);
        if (threadIdx.x == 0) g_partial[blockIdx.x] = t;
    }
}

__global__ void scanB_kernel() {   // exclusive scan of the 98 partials (1 block)
    __shared__ int s[128];
    int tid = threadIdx.x;
    int v = (tid < NB) ? g_partial[tid] : 0;
    s[tid] = v;
    __syncthreads();
    #pragma unroll
    for (int o = 1; o < 128; o <<= 1) {
        int t = (tid >= o) ? s[tid - o] : 0;
        __syncthreads();
        s[tid] += t;
        __syncthreads();
    }
    if (tid < NB) g_partial[tid] = s[tid] - v;
}

__global__ void scanC_kernel() {   // block-local exclusive scan + offset -> start/cursor
    int tid = threadIdx.x;
    int i = blockIdx.x * 1024 + tid;
    int v = (i < TOTN) ? g_count[i] : 0;
    int lane = tid & 31, wid = tid >> 5;
    int incl = v;
    #pragma unroll
    for (int o = 1; o < 32; o <<= 1) {
        int y = __shfl_up_sync(0xffffffffu, incl, o);
        if (lane >= o) incl += y;
    }
    __shared__ int wsum[32];
    if (lane == 31) wsum[wid] = incl;
    __syncthreads();
    if (tid < 32) {
        int w = wsum[tid];
        #pragma unroll
        for (int o = 1; o < 32; o <<= 1) {
            int y = __shfl_up_sync(0xffffffffu, w, o);
            if (tid >= o) w += y;
        }
        wsum[tid] = w;
    }
    __syncthreads();
    int excl = incl - v + (wid ? wsum[wid - 1] : 0) + g_partial[blockIdx.x];
    if (i < TOTN) { g_start[i] = excl; g_cursor[i] = excl; }
    if (i == 0) g_start[TOTN] = TOTE;
}

__global__ void scatter_kernel(const int* __restrict__ ei0, const float* __restrict__ ea0,
                               const int* __restrict__ ei1, const float* __restrict__ ea1) {
    int e = blockIdx.x * blockDim.x + threadIdx.x;
    if (e >= TOTE) return;
    int layer = (e >= NE);
    const int*   ei = layer ? ei1 : ei0;
    const float* ea = layer ? ea1 : ea0;
    int le = e - layer * NE;
    int dst = ei[NE + le];
    int pos = atomicAdd(&g_cursor[layer * NN + dst], 1);
    g_src_sorted[pos] = ei[le];
    const float2* s = (const float2*)(ea + (size_t)le * 6);     // 24B stride -> 8B aligned
    float2* o = (float2*)(g_ea_sorted + (size_t)pos * 6);
    o[0] = s[0]; o[1] = s[1]; o[2] = s[2];
}

// ---------------- per-node edge aggregation: f32x2 over ADJACENT CHANNEL pairs ---------
// 32 threads per node; thread t owns channels 2t, 2t+1 -> output dims 6t..6t+5.
__global__ void __launch_bounds__(256) edge_aggr_kernel(
    const float* __restrict__ x,
    const float* __restrict__ Win0, const float* __restrict__ bin0,
    const float* __restrict__ Win1, const float* __restrict__ bin1)
{
    int nid = blockIdx.x * 8 + (threadIdx.x >> 5);   // 0..TOTN-1 (TOTN % 8 == 0)
    int t = threadIdx.x & 31;
    int layer = (nid >= NN);
    const float* W_in = layer ? Win1 : Win0;
    const float* b_in = layer ? bin1 : bin0;

    // packed weights: wp[j][a] = (W[a][6t+j], W[a][6t+3+j])
    ull w0p[6], w1p[6], w2p[6];
    #pragma unroll
    for (int a = 0; a < 6; a++) {
        const float* Wr = W_in + a * KDIM + 6 * t;
        w0p[a] = pack2(Wr[0], Wr[3]);
        w1p[a] = pack2(Wr[1], Wr[4]);
        w2p[a] = pack2(Wr[2], Wr[5]);
    }
    const float* br = b_in + 6 * t;
    ull b0p = pack2(br[0], br[3]);
    ull b1p = pack2(br[1], br[4]);
    ull b2p = pack2(br[2], br[5]);

    int s = g_start[nid], eEnd = g_start[nid + 1];

    ull acc0 = 0ull, acc1 = 0ull, acc2 = 0ull;
    for (int i = s; i < eEnd; i++) {
        int srcv = g_src_sorted[i];                     // same addr across warp
        const float2* ea = (const float2*)(g_ea_sorted + (size_t)i * 6);
        float2 p0 = ea[0], p1 = ea[1], p2 = ea[2];      // same addr across warp
        ull a0 = pack2(p0.x, p0.x), a1 = pack2(p0.y, p0.y);
        ull a2 = pack2(p1.x, p1.x), a3 = pack2(p1.y, p1.y);
        ull a4 = pack2(p2.x, p2.x), a5 = pack2(p2.y, p2.y);
        ull xp = *reinterpret_cast<const ull*>(x + (size_t)srcv * CIN + 2 * t);

        ull s0 = b0p, s1 = b1p, s2 = b2p;
        fma2(s0, a0, w0p[0]); fma2(s0, a1, w0p[1]); fma2(s0, a2, w0p[2]);
        fma2(s0, a3, w0p[3]); fma2(s0, a4, w0p[4]); fma2(s0, a5, w0p[5]);
        fma2(s1, a0, w1p[0]); fma2(s1, a1, w1p[1]); fma2(s1, a2, w1p[2]);
        fma2(s1, a3, w1p[3]); fma2(s1, a4, w1p[4]); fma2(s1, a5, w1p[5]);
        fma2(s2, a0, w2p[0]); fma2(s2, a1, w2p[1]); fma2(s2, a2, w2p[2]);
        fma2(s2, a3, w2p[3]); fma2(s2, a4, w2p[4]); fma2(s2, a5, w2p[5]);

        fma2(acc0, relu2(s0), xp);
        fma2(acc1, relu2(s1), xp);
        fma2(acc2, relu2(s2), xp);
    }

    float lo0, hi0, lo1, hi1, lo2, hi2;
    unpack2(acc0, lo0, hi0);
    unpack2(acc1, lo1, hi1);
    unpack2(acc2, lo2, hi2);
    float* o = g_aggr + (size_t)nid * KDIM + 6 * t;
    o[0] = lo0; o[1] = lo1; o[2] = lo2;
    o[3] = hi0; o[4] = hi1; o[5] = hi2;
}

// ---------------- output GEMM + bias + tanh: tf32 tensor-core MMA ----------------
// block tile 128x128, BK=32, 256 threads = 8 warps as 2(m) x 4(n); warp tile 64x32.
// m16n8k8 frags: A row-major from As[r][kk], B col-major from Bs[n][kk] (transposed W).
// Pad 36: frag-load bank index = (4*group + tig) -> conflict-free.
__global__ void __launch_bounds__(256) gemm_mma_kernel(
    const float* __restrict__ Wout0, const float* __restrict__ bout0,
    const float* __restrict__ Wout1, const float* __restrict__ bout1,
    float* __restrict__ out)
{
    int layer = blockIdx.y;
    const float* Wout = layer ? Wout1 : Wout0;
    const float* bout = layer ? bout1 : bout0;
    const float* aggr = g_aggr + (size_t)layer * NN * KDIM;

    __shared__ uint32_t As[128][36];   // [row][kk] tf32 bits, 18.4 KB
    __shared__ uint32_t Bs[128][36];   // [col][kk] tf32 bits (W transposed), 18.4 KB

    int tid  = threadIdx.x;
    int lane = tid & 31;
    int warp = tid >> 5;
    int g    = lane >> 2;      // group id (row/col within frag)
    int tig  = lane & 3;       // thread in group (k within frag)
    int wm   = (warp & 1) * 64;    // warp m offset: 2 warps cover 128 rows
    int wn   = (warp >> 1) * 32;   // warp n offset: 4 warps cover 128 cols
    int n0   = blockIdx.x * 128;

    float c[4][4][4];
    #pragma unroll
    for (int fm = 0; fm < 4; fm++)
        #pragma unroll
        for (int fn = 0; fn < 4; fn++)
            #pragma unroll
            for (int k = 0; k < 4; k++) c[fm][fn][k] = 0.f;

    for (int k0 = 0; k0 < KDIM; k0 += 32) {
        // A tile: 128 rows x 32 kk, coalesced; convert to tf32 at store
        #pragma unroll
        for (int j = 0; j < 16; j++) {
            int idx = tid + 256 * j;
            int r = idx >> 5, kk = idx & 31;
            int n = n0 + r;
            float v = (n < NN) ? aggr[(size_t)n * KDIM + k0 + kk] : 0.f;
            As[r][kk] = f2tf32(v);
        }
        // B tile: W[k0+kk][cc] -> Bs[cc][kk] (transposed store)
        #pragma unroll
        for (int j = 0; j < 16; j++) {
            int idx = tid + 256 * j;
            int kk = idx >> 7, cc = idx & 127;
            Bs[cc][kk] = f2tf32(Wout[(k0 + kk) * COUT + cc]);
        }
        __syncthreads();
        #pragma unroll
        for (int ks = 0; ks < 4; ks++) {
            int kb = ks * 8;
            uint32_t a[4][4], b[4][2];
            #pragma unroll
            for (int fm = 0; fm < 4; fm++) {
                int r = wm + fm * 16 + g;
                a[fm][0] = As[r][kb + tig];
                a[fm][1] = As[r + 8][kb + tig];
                a[fm][2] = As[r][kb + tig + 4];
                a[fm][3] = As[r + 8][kb + tig + 4];
            }
            #pragma unroll
            for (int fn = 0; fn < 4; fn++) {
                int nidx = wn + fn * 8 + g;
                b[fn][0] = Bs[nidx][kb + tig];
                b[fn][1] = Bs[nidx][kb + tig + 4];
            }
            #pragma unroll
            for (int fm = 0; fm < 4; fm++)
                #pragma unroll
                for (int fn = 0; fn < 4; fn++)
                    mma_tf32(c[fm][fn], a[fm], b[fn]);
        }
        __syncthreads();
    }

    // epilogue: bias + tanh, write straight from C frags
    #pragma unroll
    for (int fn = 0; fn < 4; fn++) {
        int col = wn + fn * 8 + 2 * tig;
        float bv0 = bout[col], bv1 = bout[col + 1];
        #pragma unroll
        for (int fm = 0; fm < 4; fm++) {
            int r0 = n0 + wm + fm * 16 + g;
            size_t base = (size_t)layer * COUT + col;
            if (r0 < NN) {
                out[(size_t)r0 * (2 * COUT) + base]     = tanh_fast(c[fm][fn][0] + bv0);
                out[(size_t)r0 * (2 * COUT) + base + 1] = tanh_fast(c[fm][fn][1] + bv1);
            }
            if (r0 + 8 < NN) {
                out[(size_t)(r0 + 8) * (2 * COUT) + base]     = tanh_fast(c[fm][fn][2] + bv0);
                out[(size_t)(r0 + 8) * (2 * COUT) + base + 1] = tanh_fast(c[fm][fn][3] + bv1);
            }
        }
    }
}

extern "C" void kernel_launch(void* const* d_in, const int* in_sizes, int n_in,
                              void* d_out, int out_size) {
    const float* x     = (const float*)d_in[0];
    const int*   ei0   = (const int*)d_in[1];
    const float* ea0   = (const float*)d_in[2];
    const int*   ei1   = (const int*)d_in[3];
    const float* ea1   = (const float*)d_in[4];
    const float* Win0  = (const float*)d_in[5];
    const float* bin0  = (const float*)d_in[6];
    const float* Wout0 = (const float*)d_in[7];
    const float* bout0 = (const float*)d_in[8];
    const float* Win1  = (const float*)d_in[9];
    const float* bin1  = (const float*)d_in[10];
    const float* Wout1 = (const float*)d_in[11];
    const float* bout1 = (const float*)d_in[12];
    float* out = (float*)d_out;
    (void)in_sizes; (void)n_in; (void)out_size;

    zero_counts_kernel<<<(TOTN + 255) / 256, 256>>>();
    hist_kernel<<<(TOTE + 255) / 256, 256>>>(ei0, ei1);
    scanA_kernel<<<NB, 1024>>>();
    scanB_kernel<<<1, 128>>>();
    scanC_kernel<<<NB, 1024>>>();
    scatter_kernel<<<(TOTE + 255) / 256, 256>>>(ei0, ea0, ei1, ea1);

    edge_aggr_kernel<<<TOTN / 8, 256>>>(x, Win0, bin0, Win1, bin1);

    dim3 ggrid((NN + 127) / 128, 2);
    gemm_mma_kernel<<<ggrid, 256>>>(Wout0, bout0, Wout1, bout1, out);
}

// round 15
// speedup vs baseline: 1.4083x; 1.0234x over previous
#include <cuda_runtime.h>
#include <math.h>
#include <stdint.h>

#define NN 50000
#define NE 800000
#define CIN 64
#define KDIM 192   // HID*C_IN
#define COUT 128
#define TOTN (2 * NN)
#define TOTE (2 * NE)
#define NB ((TOTN + 1023) / 1024)   // 98 scan blocks

typedef unsigned long long ull;

// ---- static scratch (no allocations allowed) ----
__device__ int   g_count[TOTN];
__device__ int   g_start[TOTN + 1];
__device__ int   g_cursor[TOTN];
__device__ int   g_partial[128];
__device__ int2  g_se_sorted[TOTE];                     // (src, eid) 12.8 MB
__device__ float g_aggr[(size_t)TOTN * KDIM];           // 76.8 MB

// ---------- f32x2 / misc helpers ----------
__device__ __forceinline__ ull pack2(float lo, float hi) {
    ull r; asm("mov.b64 %0, {%1,%2};" : "=l"(r) : "f"(lo), "f"(hi)); return r;
}
__device__ __forceinline__ void unpack2(ull v, float& lo, float& hi) {
    asm("mov.b64 {%0,%1}, %2;" : "=f"(lo), "=f"(hi) : "l"(v));
}
__device__ __forceinline__ void fma2(ull& d, ull a, ull b) {
    asm("fma.rn.f32x2 %0, %1, %2, %0;" : "+l"(d) : "l"(a), "l"(b));
}
__device__ __forceinline__ ull relu2(ull v) {
    float lo, hi;
    unpack2(v, lo, hi);
    return pack2(fmaxf(lo, 0.f), fmaxf(hi, 0.f));
}
__device__ __forceinline__ float tanh_fast(float v) {
    float r; asm("tanh.approx.f32 %0, %1;" : "=f"(r) : "f"(v)); return r;
}
__device__ __forceinline__ uint32_t f2tf32(float f) {
    uint32_t u; asm("cvt.rna.tf32.f32 %0, %1;" : "=r"(u) : "f"(f)); return u;
}
__device__ __forceinline__ void mma_tf32(float* c, const uint32_t* a, const uint32_t* b) {
    asm("mma.sync.aligned.m16n8k8.row.col.f32.tf32.tf32.f32 "
        "{%0,%1,%2,%3}, {%4,%5,%6,%7}, {%8,%9}, {%0,%1,%2,%3};"
        : "+f"(c[0]), "+f"(c[1]), "+f"(c[2]), "+f"(c[3])
        : "r"(a[0]), "r"(a[1]), "r"(a[2]), "r"(a[3]), "r"(b[0]), "r"(b[1]));
}

// ---------------- CSR build ----------------
__global__ void zero_counts_kernel() {
    int i = blockIdx.x * blockDim.x + threadIdx.x;
    if (i < TOTN) g_count[i] = 0;
}

// edge_index is int32 on device (JAX x64 disabled -> astype(int64) is a no-op)
__global__ void hist_kernel(const int* __restrict__ ei0, const int* __restrict__ ei1) {
    int e = blockIdx.x * blockDim.x + threadIdx.x;
    if (e >= TOTE) return;
    int layer = (e >= NE);
    const int* ei = layer ? ei1 : ei0;
    int le = e - layer * NE;
    atomicAdd(&g_count[layer * NN + ei[NE + le]], 1);
}

__global__ void scanA_kernel() {   // per-block reduce -> g_partial
    int i = blockIdx.x * 1024 + threadIdx.x;
    int v = (i < TOTN) ? g_count[i] : 0;
    #pragma unroll
    for (int o = 16; o > 0; o >>= 1) v += __shfl_down_sync(0xffffffffu, v, o);
    __shared__ int ws[32];
    if ((threadIdx.x & 31) == 0) ws[threadIdx.x >> 5] = v;
    __syncthreads();
    if (threadIdx.x < 32) {
        int t = ws[threadIdx.x];
        #pragma unroll
        for (int o = 16; o > 0; o >>= 1) t += __shfl_down_sync(0xffffffffu, t, o);
        if (threadIdx.x == 0) g_partial[blockIdx.x] = t;
    }
}

__global__ void scanB_kernel() {   // exclusive scan of the 98 partials (1 block)
    __shared__ int s[128];
    int tid = threadIdx.x;
    int v = (tid < NB) ? g_partial[tid] : 0;
    s[tid] = v;
    __syncthreads();
    #pragma unroll
    for (int o = 1; o < 128; o <<= 1) {
        int t = (tid >= o) ? s[tid - o] : 0;
        __syncthreads();
        s[tid] += t;
        __syncthreads();
    }
    if (tid < NB) g_partial[tid] = s[tid] - v;
}

__global__ void scanC_kernel() {   // block-local exclusive scan + offset -> start/cursor
    int tid = threadIdx.x;
    int i = blockIdx.x * 1024 + tid;
    int v = (i < TOTN) ? g_count[i] : 0;
    int lane = tid & 31, wid = tid >> 5;
    int incl = v;
    #pragma unroll
    for (int o = 1; o < 32; o <<= 1) {
        int y = __shfl_up_sync(0xffffffffu, incl, o);
        if (lane >= o) incl += y;
    }
    __shared__ int wsum[32];
    if (lane == 31) wsum[wid] = incl;
    __syncthreads();
    if (tid < 32) {
        int w = wsum[tid];
        #pragma unroll
        for (int o = 1; o < 32; o <<= 1) {
            int y = __shfl_up_sync(0xffffffffu, w, o);
            if (tid >= o) w += y;
        }
        wsum[tid] = w;
    }
    __syncthreads();
    int excl = incl - v + (wid ? wsum[wid - 1] : 0) + g_partial[blockIdx.x];
    if (i < TOTN) { g_start[i] = excl; g_cursor[i] = excl; }
    if (i == 0) g_start[TOTN] = TOTE;
}

// lean scatter: only (src, eid) goes into CSR order; attrs stay in place, read by eid later
__global__ void scatter_kernel(const int* __restrict__ ei0, const int* __restrict__ ei1) {
    int e = blockIdx.x * blockDim.x + threadIdx.x;
    if (e >= TOTE) return;
    int layer = (e >= NE);
    const int* ei = layer ? ei1 : ei0;
    int le = e - layer * NE;
    int dst = ei[NE + le];
    int pos = atomicAdd(&g_cursor[layer * NN + dst], 1);
    g_se_sorted[pos] = make_int2(ei[le], le);
}

// ---------------- per-node edge aggregation: f32x2 over ADJACENT CHANNEL pairs ---------
// 32 threads per node; thread t owns channels 2t, 2t+1 -> output dims 6t..6t+5.
// Edge attrs read from the ORIGINAL arrays via eid (warp-uniform random LDG.64, L2-resident).
__global__ void __launch_bounds__(256) edge_aggr_kernel(
    const float* __restrict__ x,
    const float* __restrict__ ea0, const float* __restrict__ ea1,
    const float* __restrict__ Win0, const float* __restrict__ bin0,
    const float* __restrict__ Win1, const float* __restrict__ bin1)
{
    int nid = blockIdx.x * 8 + (threadIdx.x >> 5);   // 0..TOTN-1 (TOTN % 8 == 0)
    int t = threadIdx.x & 31;
    int layer = (nid >= NN);
    const float* W_in = layer ? Win1 : Win0;
    const float* b_in = layer ? bin1 : bin0;
    const float* eab  = layer ? ea1 : ea0;

    // packed weights: wp[j][a] = (W[a][6t+j], W[a][6t+3+j])
    ull w0p[6], w1p[6], w2p[6];
    #pragma unroll
    for (int a = 0; a < 6; a++) {
        const float* Wr = W_in + a * KDIM + 6 * t;
        w0p[a] = pack2(Wr[0], Wr[3]);
        w1p[a] = pack2(Wr[1], Wr[4]);
        w2p[a] = pack2(Wr[2], Wr[5]);
    }
    const float* br = b_in + 6 * t;
    ull b0p = pack2(br[0], br[3]);
    ull b1p = pack2(br[1], br[4]);
    ull b2p = pack2(br[2], br[5]);

    int s = g_start[nid], eEnd = g_start[nid + 1];

    ull acc0 = 0ull, acc1 = 0ull, acc2 = 0ull;
    for (int i = s; i < eEnd; i++) {
        int2 se = __ldg(&g_se_sorted[i]);               // (src, eid), warp-uniform
        const float2* ea = (const float2*)(eab + (size_t)se.y * 6);
        float2 p0 = __ldg(&ea[0]), p1 = __ldg(&ea[1]), p2 = __ldg(&ea[2]);
        ull a0 = pack2(p0.x, p0.x), a1 = pack2(p0.y, p0.y);
        ull a2 = pack2(p1.x, p1.x), a3 = pack2(p1.y, p1.y);
        ull a4 = pack2(p2.x, p2.x), a5 = pack2(p2.y, p2.y);
        ull xp = *reinterpret_cast<const ull*>(x + (size_t)se.x * CIN + 2 * t);

        ull s0 = b0p, s1 = b1p, s2 = b2p;
        fma2(s0, a0, w0p[0]); fma2(s0, a1, w0p[1]); fma2(s0, a2, w0p[2]);
        fma2(s0, a3, w0p[3]); fma2(s0, a4, w0p[4]); fma2(s0, a5, w0p[5]);
        fma2(s1, a0, w1p[0]); fma2(s1, a1, w1p[1]); fma2(s1, a2, w1p[2]);
        fma2(s1, a3, w1p[3]); fma2(s1, a4, w1p[4]); fma2(s1, a5, w1p[5]);
        fma2(s2, a0, w2p[0]); fma2(s2, a1, w2p[1]); fma2(s2, a2, w2p[2]);
        fma2(s2, a3, w2p[3]); fma2(s2, a4, w2p[4]); fma2(s2, a5, w2p[5]);

        fma2(acc0, relu2(s0), xp);
        fma2(acc1, relu2(s1), xp);
        fma2(acc2, relu2(s2), xp);
    }

    float lo0, hi0, lo1, hi1, lo2, hi2;
    unpack2(acc0, lo0, hi0);
    unpack2(acc1, lo1, hi1);
    unpack2(acc2, lo2, hi2);
    float* o = g_aggr + (size_t)nid * KDIM + 6 * t;
    o[0] = lo0; o[1] = lo1; o[2] = lo2;
    o[3] = hi0; o[4] = hi1; o[5] = hi2;
}

// ---------------- output GEMM + bias + tanh: tf32 tensor-core MMA ----------------
// block tile 128x128, BK=32, 256 threads = 8 warps as 2(m) x 4(n); warp tile 64x32.
__global__ void __launch_bounds__(256) gemm_mma_kernel(
    const float* __restrict__ Wout0, const float* __restrict__ bout0,
    const float* __restrict__ Wout1, const float* __restrict__ bout1,
    float* __restrict__ out)
{
    int layer = blockIdx.y;
    const float* Wout = layer ? Wout1 : Wout0;
    const float* bout = layer ? bout1 : bout0;
    const float* aggr = g_aggr + (size_t)layer * NN * KDIM;

    __shared__ uint32_t As[128][36];   // [row][kk] tf32 bits
    __shared__ uint32_t Bs[128][36];   // [col][kk] tf32 bits (W transposed)

    int tid  = threadIdx.x;
    int lane = tid & 31;
    int warp = tid >> 5;
    int g    = lane >> 2;
    int tig  = lane & 3;
    int wm   = (warp & 1) * 64;
    int wn   = (warp >> 1) * 32;
    int n0   = blockIdx.x * 128;

    float c[4][4][4];
    #pragma unroll
    for (int fm = 0; fm < 4; fm++)
        #pragma unroll
        for (int fn = 0; fn < 4; fn++)
            #pragma unroll
            for (int k = 0; k < 4; k++) c[fm][fn][k] = 0.f;

    for (int k0 = 0; k0 < KDIM; k0 += 32) {
        #pragma unroll
        for (int j = 0; j < 16; j++) {
            int idx = tid + 256 * j;
            int r = idx >> 5, kk = idx & 31;
            int n = n0 + r;
            float v = (n < NN) ? aggr[(size_t)n * KDIM + k0 + kk] : 0.f;
            As[r][kk] = f2tf32(v);
        }
        #pragma unroll
        for (int j = 0; j < 16; j++) {
            int idx = tid + 256 * j;
            int kk = idx >> 7, cc = idx & 127;
            Bs[cc][kk] = f2tf32(Wout[(k0 + kk) * COUT + cc]);
        }
        __syncthreads();
        #pragma unroll
        for (int ks = 0; ks < 4; ks++) {
            int kb = ks * 8;
            uint32_t a[4][4], b[4][2];
            #pragma unroll
            for (int fm = 0; fm < 4; fm++) {
                int r = wm + fm * 16 + g;
                a[fm][0] = As[r][kb + tig];
                a[fm][1] = As[r + 8][kb + tig];
                a[fm][2] = As[r][kb + tig + 4];
                a[fm][3] = As[r + 8][kb + tig + 4];
            }
            #pragma unroll
            for (int fn = 0; fn < 4; fn++) {
                int nidx = wn + fn * 8 + g;
                b[fn][0] = Bs[nidx][kb + tig];
                b[fn][1] = Bs[nidx][kb + tig + 4];
            }
            #pragma unroll
            for (int fm = 0; fm < 4; fm++)
                #pragma unroll
                for (int fn = 0; fn < 4; fn++)
                    mma_tf32(c[fm][fn], a[fm], b[fn]);
        }
        __syncthreads();
    }

    #pragma unroll
    for (int fn = 0; fn < 4; fn++) {
        int col = wn + fn * 8 + 2 * tig;
        float bv0 = bout[col], bv1 = bout[col + 1];
        #pragma unroll
        for (int fm = 0; fm < 4; fm++) {
            int r0 = n0 + wm + fm * 16 + g;
            size_t base = (size_t)layer * COUT + col;
            if (r0 < NN) {
                out[(size_t)r0 * (2 * COUT) + base]     = tanh_fast(c[fm][fn][0] + bv0);
                out[(size_t)r0 * (2 * COUT) + base + 1] = tanh_fast(c[fm][fn][1] + bv1);
            }
            if (r0 + 8 < NN) {
                out[(size_t)(r0 + 8) * (2 * COUT) + base]     = tanh_fast(c[fm][fn][2] + bv0);
                out[(size_t)(r0 + 8) * (2 * COUT) + base + 1] = tanh_fast(c[fm][fn][3] + bv1);
            }
        }
    }
}

extern "C" void kernel_launch(void* const* d_in, const int* in_sizes, int n_in,
                              void* d_out, int out_size) {
    const float* x     = (const float*)d_in[0];
    const int*   ei0   = (const int*)d_in[1];
    const float* ea0   = (const float*)d_in[2];
    const int*   ei1   = (const int*)d_in[3];
    const float* ea1   = (const float*)d_in[4];
    const float* Win0  = (const float*)d_in[5];
    const float* bin0  = (const float*)d_in[6];
    const float* Wout0 = (const float*)d_in[7];
    const float* bout0 = (const float*)d_in[8];
    const float* Win1  = (const float*)d_in[9];
    const float* bin1  = (const float*)d_in[10];
    const float* Wout1 = (const float*)d_in[11];
    const float* bout1 = (const float*)d_in[12];
    float* out = (float*)d_out;
    (void)in_sizes; (void)n_in; (void)out_size;

    zero_counts_kernel<<<(TOTN + 255) / 256, 256>>>();
    hist_kernel<<<(TOTE + 255) / 256, 256>>>(ei0, ei1);
    scanA_kernel<<<NB, 1024>>>();
    scanB_kernel<<<1, 128>>>();
    scanC_kernel<<<NB, 1024>>>();
    scatter_kernel<<<(TOTE + 255) / 256, 256>>>(ei0, ei1);

    edge_aggr_kernel<<<TOTN / 8, 256>>>(x, ea0, ea1, Win0, bin0, Win1, bin1);

    dim3 ggrid((NN + 127) / 128, 2);
    gemm_mma_kernel<<<ggrid, 256>>>(Wout0, bout0, Wout1, bout1, out);
}